// round 13
// baseline (speedup 1.0000x reference)
#include <cuda_runtime.h>
#include <cuda_bf16.h>
#include <math.h>
#include <stdint.h>

// ---------------- problem constants ----------------
#define B_    32
#define S_    160
#define KK_   44
#define E_    300
#define H_    256
#define V_    32000
#define G3_   768          // 3*H
#define NKEY_ 10240        // 2*B*S (keys_c ++ keys_r)
#define BS_   5120         // B*S

// ---------------- device scratch (static, no allocs) ----------------
__device__ float g_P    [V_ * 3072];
__device__ float g_bcat [3072];
__device__ __nv_bfloat16 g_emb2 [V_ * 640];       // emb split [hi|lo], Kpad=320 (wrapA)
__device__ __nv_bfloat16 g_Wpre2[4 * 768 * 960];  // kWif,kWib,eWif,eWib [hi|hi|lo]
__device__ __nv_bfloat16 g_Whk2 [2 * 768 * 768];  // kWhf,kWhb [hi|hi|lo]
__device__ __nv_bfloat16 g_eW2  [2 * 768 * 768];  // eWif[:,300:],eWib[:,300:] [hi|hi|lo]
__device__ __nv_bfloat16 g_h2 [2 * NKEY_ * 512];  // key GRU hidden split [hi|lo] (wrapA)
__device__ float g_gh   [2 * NKEY_ * G3_];        // key GRU gh temp (bias included)
__device__ __nv_bfloat16 g_ksum2[NKEY_ * 512];    // (hf+hb) split [hi|lo]
__device__ float g_gix  [2 * BS_ * 1536];         // enc input proj
__device__ float g_eh   [4 * B_ * H_];
__device__ float g_sc   [BS_ * 512];
__device__ float g_a    [BS_ * 512];
__device__ float g_energy[BS_];
__device__ float g_alpha [BS_];
__device__ float g_r    [B_ * 512];
__device__ float g_cattn[B_ * 512];
__device__ unsigned g_barCnt4[4];                 // encoder per-stream barriers
__device__ unsigned g_tileCnt[160];               // key GEMM m-tile completion (monotonic)

// ======================= PTX helpers ==============================
__device__ __forceinline__ uint32_t smem_u32(const void* p)
{
    return (uint32_t)__cvta_generic_to_shared(p);
}

__device__ __forceinline__ void ldsm_x4(uint32_t& r0, uint32_t& r1,
                                        uint32_t& r2, uint32_t& r3, uint32_t addr)
{
    asm volatile("ldmatrix.sync.aligned.m8n8.x4.shared.b16 {%0,%1,%2,%3},[%4];"
                 : "=r"(r0), "=r"(r1), "=r"(r2), "=r"(r3) : "r"(addr));
}

__device__ __forceinline__ void mma16816(float* c, const uint32_t* a, const uint32_t* b)
{
    asm volatile("mma.sync.aligned.m16n8k16.row.col.f32.bf16.bf16.f32 "
                 "{%0,%1,%2,%3},{%4,%5,%6,%7},{%8,%9},{%0,%1,%2,%3};"
                 : "+f"(c[0]), "+f"(c[1]), "+f"(c[2]), "+f"(c[3])
                 : "r"(a[0]), "r"(a[1]), "r"(a[2]), "r"(a[3]), "r"(b[0]), "r"(b[1]));
}

#define CP16(dst, src) asm volatile("cp.async.cg.shared.global [%0],[%1],16;" :: "r"(dst), "l"(src))
#define CPCOMMIT()     asm volatile("cp.async.commit_group;")

// swizzled chunk layout: row stride 32 elems (64B); STS and ldsm conflict-free.
#define SWZ(r, c) (((r) * 32) + ((((c) ^ (((r) >> 1) & 3))) * 8))
#define GW64_SMEM  65536   // 4-stage x (128 A + 128 B) x 32 x 2B
__device__ __forceinline__ float sigf(float x) { return 1.f / (1.f + __expf(-x)); }

// ======================= unified HMMA GEMM: 4 warps, 64x64 warp tile ======
// C(MxN) = A(MxK2,bf16) @ W(NxK2,bf16)^T (+bias) (+P[idx[m]] gather epilogue)
// Key mode (kc != nullptr): dual weight by m0, and after the epilogue the
// last-finishing n-tile block of each m-tile runs the GRU gates in-kernel.
__global__ __launch_bounds__(128, 2) void gemm_w64(
    int M, int N, int K2, int wrapA,
    const __nv_bfloat16* __restrict__ A, int lda,
    const __nv_bfloat16* __restrict__ W, int ldw,
    const float* __restrict__ bias,
    const __nv_bfloat16* __restrict__ W2, const float* __restrict__ bias2, int Msplit,
    float* __restrict__ C, int ldc,
    const int* __restrict__ idx,
    const float* __restrict__ P, int ldP, int pOff,
    const int* __restrict__ kc, const int* __restrict__ kr, int tstep)
{
    extern __shared__ __nv_bfloat16 smw[];
    __nv_bfloat16* Abuf = smw;                    // [4][128*32]
    __nv_bfloat16* Bbuf = smw + 4 * 128 * 32;     // [4][128*32]
    __shared__ int keys_s[128];
    __shared__ int finflag;

    const int m0 = blockIdx.y * 128, n0 = blockIdx.x * 128;
    const __nv_bfloat16* Wp = W;
    const float* bp = bias;
    if (W2 && m0 >= Msplit) { Wp = W2; bp = bias2; }

    const int t = threadIdx.x;
    const int lane = t & 31, warp = t >> 5;
    const int wm = (warp & 1) * 64;
    const int wn = (warp >> 1) * 64;

    float acc[4][8][4];
#pragma unroll
    for (int i = 0; i < 4; i++)
#pragma unroll
        for (int j = 0; j < 8; j++)
#pragma unroll
            for (int k = 0; k < 4; k++) acc[i][j][k] = 0.f;

    const int iters = K2 / 32;

#define PFW(kt, buf)                                                               \
    {                                                                              \
        int kb  = (kt) * 32;                                                       \
        int kbA = (wrapA && kb >= wrapA) ? kb - wrapA : kb;                        \
        _Pragma("unroll")                                                          \
        for (int i = 0; i < 4; i++) {                                              \
            int li = t + i * 128;                                                  \
            int r  = li >> 2;                                                      \
            int c4 = li & 3;                                                       \
            int so = SWZ(r, c4);                                                   \
            CP16(smem_u32(&Abuf[(buf) * 128 * 32 + so]),                           \
                 A + (size_t)(m0 + r) * lda + kbA + c4 * 8);                       \
            CP16(smem_u32(&Bbuf[(buf) * 128 * 32 + so]),                           \
                 Wp + (size_t)(n0 + r) * ldw + kb + c4 * 8);                       \
        }                                                                          \
        CPCOMMIT();                                                                \
    }

    PFW(0, 0);
    if (iters > 1) PFW(1, 1);
    if (iters > 2) PFW(2, 2);

    for (int kt = 0; kt < iters; kt++) {
        int rem = iters - kt;
        if (rem >= 3)      asm volatile("cp.async.wait_group 2;");
        else if (rem == 2) asm volatile("cp.async.wait_group 1;");
        else               asm volatile("cp.async.wait_group 0;");
        __syncthreads();

        if (kt + 3 < iters) PFW(kt + 3, (kt + 3) & 3);

        const __nv_bfloat16* as = Abuf + (kt & 3) * 128 * 32;
        const __nv_bfloat16* ws = Bbuf + (kt & 3) * 128 * 32;
#pragma unroll
        for (int ks = 0; ks < 32; ks += 16) {
            uint32_t af[4][4];
#pragma unroll
            for (int mf = 0; mf < 4; mf++) {
                int arow = wm + mf * 16 + (lane & 15);
                int cidx = (ks >> 3) + (lane >> 4);
                uint32_t ad = smem_u32(&as[SWZ(arow, cidx)]);
                ldsm_x4(af[mf][0], af[mf][1], af[mf][2], af[mf][3], ad);
            }
            uint32_t bfr[8][2];
#pragma unroll
            for (int p = 0; p < 4; p++) {
                int nrow = wn + p * 16 + ((lane >> 4) & 1) * 8 + (lane & 7);
                int cidx = (ks >> 3) + ((lane >> 3) & 1);
                uint32_t ad = smem_u32(&ws[SWZ(nrow, cidx)]);
                uint32_t b0, b1, b2, b3;
                ldsm_x4(b0, b1, b2, b3, ad);
                bfr[p * 2][0] = b0; bfr[p * 2][1] = b1;
                bfr[p * 2 + 1][0] = b2; bfr[p * 2 + 1][1] = b3;
            }
#pragma unroll
            for (int mf = 0; mf < 4; mf++)
#pragma unroll
                for (int nf = 0; nf < 8; nf++)
                    mma16816(acc[mf][nf], af[mf], bfr[nf]);
        }
    }

    // epilogue
#pragma unroll
    for (int mf = 0; mf < 4; mf++) {
#pragma unroll
        for (int half = 0; half < 2; half++) {
            int row = m0 + wm + mf * 16 + (lane >> 2) + half * 8;
            const float* prow = nullptr;
            if (idx) prow = P + (size_t)idx[row] * ldP + pOff;
#pragma unroll
            for (int nf = 0; nf < 8; nf++) {
                int col = n0 + wn + nf * 8 + (lane & 3) * 2;
                float v0 = acc[mf][nf][half * 2 + 0];
                float v1 = acc[mf][nf][half * 2 + 1];
                if (bp)   { v0 += bp[col];   v1 += bp[col + 1]; }
                if (prow) { v0 += prow[col]; v1 += prow[col + 1]; }
                float2 o; o.x = v0; o.y = v1;
                *(float2*)(C + (size_t)row * ldc + col) = o;
            }
        }
    }

    // ---- key-mode finisher: last n-tile block of this m-tile runs gates ----
    if (kc) {
        __threadfence();                       // each thread's gh stores visible
        __syncthreads();
        if (t == 0) {
            unsigned old = atomicAdd(&g_tileCnt[blockIdx.y], 1u);
            finflag = (((old + 1) % 6u) == 0u);
        }
        __syncthreads();
        if (!finflag) return;
        __threadfence();                       // acquire: see peers' gh stores

        const int dir = (m0 >= NKEY_) ? 1 : 0;
        const int nb  = m0 - dir * NKEY_;
        const int te  = dir ? (KK_ - 1 - tstep) : tstep;
        if (t < 128) {
            int n = nb + t;
            keys_s[t] = (n < BS_) ? kc[n * KK_ + te] : kr[(n - BS_) * KK_ + te];
        }
        __syncthreads();

        const int c = t * 2;                   // 2 channels per thread
        const float* ghbase = g_gh + (size_t)dir * NKEY_ * G3_;
        for (int r = 0; r < 128; r++) {
            int n = nb + r;
            const float* gh = ghbase + (size_t)n * G3_;
            const float* gi = g_P + (size_t)keys_s[r] * 3072 + dir * 768;
            float2 hr = __ldcg((const float2*)(gh + c));
            float2 hz = __ldcg((const float2*)(gh + 256 + c));
            float2 hn = __ldcg((const float2*)(gh + 512 + c));
            float2 ir = *(const float2*)(gi + c);
            float2 iz = *(const float2*)(gi + 256 + c);
            float2 in_ = *(const float2*)(gi + 512 + c);
            __nv_bfloat16* h2 = g_h2 + (size_t)(dir * NKEY_ + n) * 512;
            __nv_bfloat162 phi = *(const __nv_bfloat162*)(h2 + c);
            __nv_bfloat162 plo = *(const __nv_bfloat162*)(h2 + 256 + c);
            float hp0 = __bfloat162float(phi.x) + __bfloat162float(plo.x);
            float hp1 = __bfloat162float(phi.y) + __bfloat162float(plo.y);

            float rr0 = sigf(ir.x + hr.x), rr1 = sigf(ir.y + hr.y);
            float zz0 = sigf(iz.x + hz.x), zz1 = sigf(iz.y + hz.y);
            float nn0 = tanhf(in_.x + rr0 * hn.x);
            float nn1 = tanhf(in_.y + rr1 * hn.y);
            float hv0 = (1.f - zz0) * nn0 + zz0 * hp0;
            float hv1 = (1.f - zz1) * nn1 + zz1 * hp1;
            __nv_bfloat16 h0 = __float2bfloat16(hv0);
            __nv_bfloat16 h1 = __float2bfloat16(hv1);
            __nv_bfloat162 ohi, olo;
            ohi.x = h0; ohi.y = h1;
            olo.x = __float2bfloat16(hv0 - __bfloat162float(h0));
            olo.y = __float2bfloat16(hv1 - __bfloat162float(h1));
            *(__nv_bfloat162*)(h2 + c)       = ohi;
            *(__nv_bfloat162*)(h2 + 256 + c) = olo;
        }
    }
}

static inline void mgemm(int M, int N, int K2, int wrapA,
                         const __nv_bfloat16* A, int lda,
                         const __nv_bfloat16* W, int ldw, const float* bias,
                         float* C, int ldc,
                         const int* idx = nullptr, const float* P = nullptr,
                         int ldP = 0, int pOff = 0,
                         const __nv_bfloat16* W2 = nullptr, const float* b2 = nullptr,
                         int Msplit = 0,
                         const int* kc = nullptr, const int* kr = nullptr, int tstep = 0)
{
    dim3 g(N / 128, M / 128);
    gemm_w64<<<g, 128, GW64_SMEM>>>(M, N, K2, wrapA, A, lda, W, ldw, bias,
                                    W2, b2, Msplit, C, ldc, idx, P, ldP, pOff,
                                    kc, kr, tstep);
}

// ---------------- t=0 key gates (h=0, gh=bias) ----------------
__global__ void key_gates0_kernel(const int* __restrict__ keys_c,
                                  const int* __restrict__ keys_r,
                                  const float* __restrict__ bhf,
                                  const float* __restrict__ bhb)
{
    int n   = blockIdx.x;
    int c   = threadIdx.x;
    int dir = blockIdx.y;
    int te  = (dir == 0) ? 0 : (KK_ - 1);
    int key = (n < BS_) ? keys_c[n * KK_ + te] : keys_r[(n - BS_) * KK_ + te];

    const float* gi = g_P + (size_t)key * 3072 + dir * 768;
    const float* bb = dir ? bhb : bhf;
    float ir = gi[c], iz = gi[256 + c], in = gi[512 + c];
    float r  = sigf(ir + bb[c]);
    float z  = sigf(iz + bb[256 + c]);
    float nn = tanhf(in + r * bb[512 + c]);
    float hv = (1.f - z) * nn;

    __nv_bfloat16 hi = __float2bfloat16(hv);
    __nv_bfloat16 lo = __float2bfloat16(hv - __bfloat162float(hi));
    __nv_bfloat16* h2 = g_h2 + (size_t)(dir * NKEY_ + n) * 512;
    h2[c] = hi; h2[256 + c] = lo;
}

__global__ void ksum2_kernel()
{
    int i = blockIdx.x * blockDim.x + threadIdx.x;
    if (i >= NKEY_ * H_) return;
    int n = i >> 8, c = i & 255;
    const __nv_bfloat16* hf = g_h2 + (size_t)n * 512;
    const __nv_bfloat16* hb = g_h2 + (size_t)(NKEY_ + n) * 512;
    float s = __bfloat162float(hf[c]) + __bfloat162float(hf[256 + c])
            + __bfloat162float(hb[c]) + __bfloat162float(hb[256 + c]);
    __nv_bfloat16 hi = __float2bfloat16(s);
    __nv_bfloat16 lo = __float2bfloat16(s - __bfloat162float(hi));
    __nv_bfloat16* y = g_ksum2 + (size_t)n * 512;
    y[c] = hi; y[256 + c] = lo;
}

// ---------------- unified prep: zeros + splits + bias concat ----------------
__global__ void prep_kernel(const float* __restrict__ emb,
                            const float* kWif, const float* kWib,
                            const float* eWif, const float* eWib,
                            const float* kWhf, const float* kWhb,
                            const float* kbif, const float* kbib,
                            const float* ebif, const float* ebib)
{
    const int N_EH  = 4 * B_ * H_;
    const int N_EMB = V_ * 320;
    const int SZP = 768 * 320, SZH = 768 * 256;
    const int N_W = 4 * SZP + 4 * SZH;
    const int total = N_EH + N_EMB + N_W + 3072;

    for (int i = blockIdx.x * blockDim.x + threadIdx.x; i < total;
         i += gridDim.x * blockDim.x) {
        int j = i;
        if (j < N_EH) { g_eh[j] = 0.f; continue; }
        j -= N_EH;
        if (j < N_EMB) {
            int r = j / 320, c = j - r * 320;
            float x = (c < 300) ? emb[(size_t)r * 300 + c] : 0.f;
            __nv_bfloat16 hi = __float2bfloat16(x);
            __nv_bfloat16 lo = __float2bfloat16(x - __bfloat162float(hi));
            __nv_bfloat16* y = g_emb2 + (size_t)r * 640;
            y[c] = hi; y[320 + c] = lo;
            continue;
        }
        j -= N_EMB;
        if (j < N_W) {
            if (j < 4 * SZP) {
                int seg = j / SZP, loc = j - seg * SZP;
                const int Kpad = 320, Cc = 300;
                const float* srcs[4] = {kWif, kWib, eWif, eWib};
                int lds[4] = {300, 300, 556, 556};
                const float* X = srcs[seg]; int ldx = lds[seg];
                __nv_bfloat16* Y = g_Wpre2 + (size_t)seg * 768 * 960;
                int r = loc / Kpad, c = loc - r * Kpad;
                float x = (c < Cc) ? X[(size_t)r * ldx + c] : 0.f;
                __nv_bfloat16 hi = __float2bfloat16(x);
                __nv_bfloat16 lo = __float2bfloat16(x - __bfloat162float(hi));
                __nv_bfloat16* y = Y + (size_t)r * 3 * Kpad;
                y[c] = hi; y[Kpad + c] = hi; y[2 * Kpad + c] = lo;
            } else {
                int jj = j - 4 * SZP;
                int seg = jj / SZH, loc = jj - seg * SZH;
                const int Kpad = 256;
                int r = loc / Kpad, c = loc - r * Kpad;
                const float* X; int ldx; __nv_bfloat16* Y;
                if (seg < 2) { X = seg ? kWhb : kWhf; ldx = 256;
                               Y = g_Whk2 + (size_t)seg * 768 * 768; }
                else         { X = (seg == 2) ? (eWif + 300) : (eWib + 300); ldx = 556;
                               Y = g_eW2 + (size_t)(seg - 2) * 768 * 768; }
                float x = X[(size_t)r * ldx + c];
                __nv_bfloat16 hi = __float2bfloat16(x);
                __nv_bfloat16 lo = __float2bfloat16(x - __bfloat162float(hi));
                __nv_bfloat16* y = Y + (size_t)r * 3 * Kpad;
                y[c] = hi; y[Kpad + c] = hi; y[2 * Kpad + c] = lo;
            }
            continue;
        }
        j -= N_W;
        float v;
        if      (j < 768)  v = kbif[j];
        else if (j < 1536) v = kbib[j - 768];
        else if (j < 2304) v = ebif[j - 1536];
        else               v = ebib[j - 2304];
        g_bcat[j] = v;
    }
}

// ---------------- persistent encoder BiGRU (per-stream barriers) ----------
__device__ __forceinline__ void gridbar_st(int st)
{
    __syncthreads();
    if (threadIdx.x == 0) {
        __threadfence();
        unsigned prev = atomicAdd(&g_barCnt4[st], 1u);
        unsigned target = (prev / 32u + 1u) * 32u;
        while (*(volatile unsigned*)&g_barCnt4[st] < target) { }
    }
    __syncthreads();
}

__global__ __launch_bounds__(256, 1) void enc_persistent_kernel(
    const float* __restrict__ Whf, const float* __restrict__ Whb,
    const float* __restrict__ bhf, const float* __restrict__ bhb)
{
    __shared__ float Hs[32][260];
    __shared__ float Wsh[24][260];
    __shared__ float bsh[24];

    const int t    = threadIdx.x;
    const int b    = blockIdx.x;
    const int st   = b & 3;
    const int c0   = (b >> 2) * 8;
    const float* Wh = (st & 1) ? Whb : Whf;
    const float* bh = (st & 1) ? bhb : bhf;
    const float* gix = g_gix + (size_t)(st >> 1) * BS_ * 1536;
    const int gbase = (st & 1) * 768;
    float* ehp = g_eh + st * B_ * H_;

    for (int li = t; li < 24 * 64; li += 256) {
        int r = li >> 6, kq = (li & 63) * 4;
        int wrow = (r >> 3) * 256 + c0 + (r & 7);
        *(float4*)&Wsh[r][kq] = *(const float4*)(Wh + (size_t)wrow * H_ + kq);
    }
    if (t < 24) bsh[t] = bh[(t >> 3) * 256 + c0 + (t & 7)];
    __syncthreads();

    const int lane = t & 31;
    const int warp = t >> 5;
    const int ch = c0 + warp;

    for (int step = 0; step < S_; step++) {
        for (int li = t; li < 32 * 64; li += 256) {
            int r = li >> 6, kq = (li & 63) * 4;
            float4 v = __ldcg((const float4*)(ehp + r * H_ + kq));
            *(float4*)&Hs[r][kq] = v;
        }
        __syncthreads();

        float accR = 0.f, accZ = 0.f, accN = 0.f;
#pragma unroll 8
        for (int k = 0; k < 64; k++) {
            float4 hv = *(const float4*)&Hs[lane][k * 4];
            float4 wr = *(const float4*)&Wsh[warp][k * 4];
            float4 wz = *(const float4*)&Wsh[8 + warp][k * 4];
            float4 wn = *(const float4*)&Wsh[16 + warp][k * 4];
            accR += hv.x*wr.x + hv.y*wr.y + hv.z*wr.z + hv.w*wr.w;
            accZ += hv.x*wz.x + hv.y*wz.y + hv.z*wz.z + hv.w*wz.w;
            accN += hv.x*wn.x + hv.y*wn.y + hv.z*wn.z + hv.w*wn.w;
        }

        int s   = (st & 1) ? (S_ - 1 - step) : step;
        int row = lane * S_ + s;
        const float* gi = gix + (size_t)row * 1536 + gbase;
        float ir = gi[ch], iz = gi[256 + ch], in = gi[512 + ch];
        float r  = sigf(ir + accR + bsh[warp]);
        float z  = sigf(iz + accZ + bsh[8 + warp]);
        float nn = tanhf(in + r * (accN + bsh[16 + warp]));
        float hv = (1.f - z) * nn + z * Hs[lane][ch];
        ehp[lane * H_ + ch] = hv;
        if (st == 0)      g_sc[(size_t)row * 512 + ch]       = hv;
        else if (st == 1) g_sc[(size_t)row * 512 + 256 + ch] = hv;

        gridbar_st(st);
    }
}

__global__ void rcopy_kernel()
{
    int i = blockIdx.x * blockDim.x + threadIdx.x;
    int b = i >> 9, c = i & 511;
    g_r[i] = (c < 256) ? g_eh[2 * B_ * H_ + b * 256 + c]
                       : g_eh[3 * B_ * H_ + b * 256 + (c - 256)];
}

// ---------------- SIMT GEMM for attention ----------------
__global__ __launch_bounds__(256) void gemm_sm(
    int M, int N, int K,
    const float* __restrict__ A, int lda,
    const float* __restrict__ W, int ldw,
    const float* __restrict__ bias,
    float* __restrict__ C, int ldc)
{
    __shared__ float Asx[16][128];
    __shared__ float Wsx[16][64];

    const int m0 = blockIdx.y * 128;
    const int n0 = blockIdx.x * 64;
    const int t  = threadIdx.x;
    const int tx = t & 15;
    const int ty = t >> 4;

    float acc[8][4];
#pragma unroll
    for (int i = 0; i < 8; i++)
#pragma unroll
        for (int j = 0; j < 4; j++) acc[i][j] = 0.f;

    for (int k0 = 0; k0 < K; k0 += 16) {
#pragma unroll
        for (int i = 0; i < 2; i++) {
            int li  = t + i * 256;
            int row = li >> 2;
            int kq  = (li & 3) * 4;
            float4 v = *(const float4*)(A + (size_t)(m0 + row) * lda + k0 + kq);
            Asx[kq + 0][row] = v.x; Asx[kq + 1][row] = v.y;
            Asx[kq + 2][row] = v.z; Asx[kq + 3][row] = v.w;
        }
        {
            int row = t >> 2;
            int kq  = (t & 3) * 4;
            float4 v = *(const float4*)(W + (size_t)(n0 + row) * ldw + k0 + kq);
            Wsx[kq + 0][row] = v.x; Wsx[kq + 1][row] = v.y;
            Wsx[kq + 2][row] = v.z; Wsx[kq + 3][row] = v.w;
        }
        __syncthreads();
#pragma unroll
        for (int kk = 0; kk < 16; kk++) {
            float4 a0 = *(const float4*)&Asx[kk][ty * 8];
            float4 a1 = *(const float4*)&Asx[kk][ty * 8 + 4];
            float4 w  = *(const float4*)&Wsx[kk][tx * 4];
            float av[8] = {a0.x, a0.y, a0.z, a0.w, a1.x, a1.y, a1.z, a1.w};
            float wv[4] = {w.x, w.y, w.z, w.w};
#pragma unroll
            for (int i = 0; i < 8; i++)
#pragma unroll
                for (int j = 0; j < 4; j++) acc[i][j] += av[i] * wv[j];
        }
        __syncthreads();
    }

#pragma unroll
    for (int i = 0; i < 8; i++) {
        int row = m0 + ty * 8 + i;
        float4 o;
        o.x = acc[i][0] + bias[n0 + tx * 4 + 0];
        o.y = acc[i][1] + bias[n0 + tx * 4 + 1];
        o.z = acc[i][2] + bias[n0 + tx * 4 + 2];
        o.w = acc[i][3] + bias[n0 + tx * 4 + 3];
        *(float4*)(C + (size_t)row * ldc + n0 + tx * 4) = o;
    }
}

// ---------------- attention tail ----------------
__device__ __forceinline__ float blockReduceSum(float v)
{
    __shared__ float sh[32];
    for (int o = 16; o; o >>= 1) v += __shfl_down_sync(0xffffffffu, v, o);
    int lane = threadIdx.x & 31, w = threadIdx.x >> 5;
    if (lane == 0) sh[w] = v;
    __syncthreads();
    int nw = (blockDim.x + 31) >> 5;
    v = (w == 0 && lane < nw) ? sh[lane] : 0.f;
    if (w == 0)
        for (int o = 16; o; o >>= 1) v += __shfl_down_sync(0xffffffffu, v, o);
    return v;
}

__global__ void energy_kernel()
{
    int bs = blockIdx.x;
    int b  = bs / S_;
    float p = 0.f;
    for (int k = threadIdx.x; k < 512; k += 128)
        p += g_a[(size_t)bs * 512 + k] * g_r[b * 512 + k];
    float s = blockReduceSum(p);
    if (threadIdx.x == 0) g_energy[bs] = s;
}

__global__ void softmax_kernel(const float* __restrict__ mask)
{
    int b = blockIdx.x;
    __shared__ float ex[S_];
    __shared__ float smx, ssum;
    int tid = threadIdx.x;
    if (tid < S_) ex[tid] = g_energy[b * S_ + tid];
    __syncthreads();
    if (tid == 0) { float m = -1e30f; for (int s = 0; s < S_; s++) m = fmaxf(m, ex[s]); smx = m; }
    __syncthreads();
    if (tid < S_) ex[tid] = __expf(ex[tid] - smx);
    __syncthreads();
    if (tid == 0) { float s = 0.f; for (int i = 0; i < S_; i++) s += ex[i]; ssum = s; }
    __syncthreads();
    if (tid < S_) g_alpha[b * S_ + tid] = ex[tid] / ssum * mask[b * S_ + tid];
}

__global__ void cattn_kernel()
{
    int b = blockIdx.x, d = threadIdx.x;
    float acc = 0.f;
    for (int s = 0; s < S_; s++)
        acc += g_alpha[b * S_ + s] * g_sc[(size_t)(b * S_ + s) * 512 + d];
    g_cattn[b * 512 + d] = acc;
}

__global__ void final_kernel(const float* __restrict__ Mm,
                             const float* __restrict__ b0,
                             float* __restrict__ out)
{
    int b = blockIdx.x;
    float part = 0.f;
    for (int d = threadIdx.x; d < 512; d += 256) {
        const float* mr = Mm + (size_t)d * 512;
        const float* rr = g_r + b * 512;
        float td = 0.f;
        for (int e = 0; e < 512; e++) td += mr[e] * rr[e];
        part += g_cattn[b * 512 + d] * td;
    }
    float s = blockReduceSum(part);
    if (threadIdx.x == 0) out[b] = s + b0[0];
}

// ---------------- host orchestration ----------------
extern "C" void kernel_launch(void* const* d_in, const int* in_sizes, int n_in,
                              void* d_out, int out_size)
{
    const int*   x1     = (const int*)d_in[0];
    const int*   x2     = (const int*)d_in[1];
    const int*   keys_c = (const int*)d_in[2];
    const int*   keys_r = (const int*)d_in[3];
    const float* x1mask = (const float*)d_in[4];
    const float* emb    = (const float*)d_in[5];
    const float* kWif   = (const float*)d_in[6];
    const float* kWhf   = (const float*)d_in[7];
    const float* kbif   = (const float*)d_in[8];
    const float* kbhf   = (const float*)d_in[9];
    const float* kWib   = (const float*)d_in[10];
    const float* kWhb   = (const float*)d_in[11];
    const float* kbib   = (const float*)d_in[12];
    const float* kbhb   = (const float*)d_in[13];
    const float* eWif   = (const float*)d_in[14];
    const float* eWhf   = (const float*)d_in[15];
    const float* ebif   = (const float*)d_in[16];
    const float* ebhf   = (const float*)d_in[17];
    const float* eWib   = (const float*)d_in[18];
    const float* eWhb   = (const float*)d_in[19];
    const float* ebib   = (const float*)d_in[20];
    const float* ebhb   = (const float*)d_in[21];
    const float* attn_W = (const float*)d_in[22];
    const float* attn_b = (const float*)d_in[23];
    const float* Mm     = (const float*)d_in[24];
    const float* b0     = (const float*)d_in[25];
    float* out = (float*)d_out;

    float *pP, *pBcat, *pGix, *pSc, *pA, *pGH;
    __nv_bfloat16 *pEmb2, *pWpre2, *pWhk2, *pEW2, *pH2, *pKsum2;
    cudaGetSymbolAddress((void**)&pP,     g_P);
    cudaGetSymbolAddress((void**)&pBcat,  g_bcat);
    cudaGetSymbolAddress((void**)&pGix,   g_gix);
    cudaGetSymbolAddress((void**)&pSc,    g_sc);
    cudaGetSymbolAddress((void**)&pA,     g_a);
    cudaGetSymbolAddress((void**)&pGH,    g_gh);
    cudaGetSymbolAddress((void**)&pEmb2,  g_emb2);
    cudaGetSymbolAddress((void**)&pWpre2, g_Wpre2);
    cudaGetSymbolAddress((void**)&pWhk2,  g_Whk2);
    cudaGetSymbolAddress((void**)&pEW2,   g_eW2);
    cudaGetSymbolAddress((void**)&pH2,    g_h2);
    cudaGetSymbolAddress((void**)&pKsum2, g_ksum2);

    cudaFuncSetAttribute(gemm_w64, cudaFuncAttributeMaxDynamicSharedMemorySize,
                         GW64_SMEM);

    // 0: unified prep (zeros + bf16 splits + bias concat)
    prep_kernel<<<8192, 256>>>(emb, kWif, kWib, eWif, eWib, kWhf, kWhb,
                               kbif, kbib, ebif, ebib);

    // 1: unified precompute GEMM  g_P = emb2 @ [kWif;kWib;eWif;eWib]^T + bcat
    mgemm(V_, 3072, 960, 640, pEmb2, 640, pWpre2, 960, pBcat, pP, 3072);

    // 2: key BiGRU t=0 (h=0 -> gh=bias)
    key_gates0_kernel<<<dim3(NKEY_, 2), 256>>>(keys_c, keys_r, kbhf, kbhb);

    // 3..: key steps: dual-weight HMMA GEMM with in-kernel gates finisher
    for (int t = 1; t < KK_; t++)
        mgemm(2 * NKEY_, G3_, 768, 512, pH2, 512, pWhk2, 768, kbhf, pGH, G3_,
              nullptr, nullptr, 0, 0, pWhk2 + 768 * 768, kbhb, NKEY_,
              keys_c, keys_r, t);

    ksum2_kernel<<<(NKEY_ * H_ + 255) / 256, 256>>>();

    // encoder input projections: 2 batched GEMMs (f||b), Penc gather epilogue
    mgemm(BS_, 1536, 768, 512, pKsum2,             512, pEW2, 768, nullptr,
          pGix,                      1536, x1, pP, 3072, 1536);
    mgemm(BS_, 1536, 768, 512, pKsum2 + BS_ * 512, 512, pEW2, 768, nullptr,
          pGix + (size_t)BS_ * 1536, 1536, x2, pP, 3072, 1536);

    // encoder BiGRU: persistent, per-stream barriers
    enc_persistent_kernel<<<128, 256>>>(eWhf, eWhb, ebhf, ebhb);
    rcopy_kernel<<<64, 256>>>();

    // attention + output
    {
        dim3 g(512 / 64, BS_ / 128);
        gemm_sm<<<g, 256>>>(BS_, 512, 512, pSc, 512, attn_W, 512, attn_b, pA, 512);
    }
    energy_kernel<<<BS_, 128>>>();
    softmax_kernel<<<B_, 192>>>(x1mask);
    cattn_kernel<<<B_, 512>>>();
    final_kernel<<<B_, 256>>>(Mm, b0, out);
}

// round 14
// speedup vs baseline: 1.9663x; 1.9663x over previous
#include <cuda_runtime.h>
#include <cuda_bf16.h>
#include <math.h>
#include <stdint.h>

// ---------------- problem constants ----------------
#define B_    32
#define S_    160
#define KK_   44
#define E_    300
#define H_    256
#define V_    32000
#define G3_   768          // 3*H
#define NKEY_ 10240        // 2*B*S (keys_c ++ keys_r)
#define BS_   5120         // B*S

// ---------------- device scratch (static, no allocs) ----------------
__device__ float g_P    [V_ * 3072];
__device__ float g_bcat [3072];
__device__ __nv_bfloat16 g_emb2 [V_ * 640];       // emb split [hi|lo], Kpad=320 (wrapA)
__device__ __nv_bfloat16 g_Wpre2[4 * 768 * 960];  // kWif,kWib,eWif,eWib [hi|hi|lo]
__device__ __nv_bfloat16 g_Whk2 [2 * 768 * 768];  // kWhf,kWhb [hi|hi|lo]
__device__ __nv_bfloat16 g_eW2  [2 * 768 * 768];  // eWif[:,300:],eWib[:,300:] [hi|hi|lo]
__device__ __nv_bfloat16 g_h2 [2 * NKEY_ * 512];  // key GRU hidden split [hi|lo] (wrapA)
__device__ float g_gh   [2 * NKEY_ * G3_];        // key GRU gh temp
__device__ __nv_bfloat16 g_ksum2[NKEY_ * 512];    // (hf+hb) split [hi|lo]
__device__ float g_gix  [2 * BS_ * 1536];         // enc input proj
__device__ float g_eh   [4 * B_ * H_];
__device__ float g_sc   [BS_ * 512];
__device__ float g_a    [BS_ * 512];
__device__ float g_energy[BS_];
__device__ float g_alpha [BS_];
__device__ float g_r    [B_ * 512];
__device__ float g_cattn[B_ * 512];
__device__ unsigned g_barCnt4[4];                 // encoder per-stream barriers

// ======================= PTX helpers ==============================
__device__ __forceinline__ uint32_t smem_u32(const void* p)
{
    return (uint32_t)__cvta_generic_to_shared(p);
}

__device__ __forceinline__ void ldsm_x4(uint32_t& r0, uint32_t& r1,
                                        uint32_t& r2, uint32_t& r3, uint32_t addr)
{
    asm volatile("ldmatrix.sync.aligned.m8n8.x4.shared.b16 {%0,%1,%2,%3},[%4];"
                 : "=r"(r0), "=r"(r1), "=r"(r2), "=r"(r3) : "r"(addr));
}

__device__ __forceinline__ void mma16816(float* c, const uint32_t* a, const uint32_t* b)
{
    asm volatile("mma.sync.aligned.m16n8k16.row.col.f32.bf16.bf16.f32 "
                 "{%0,%1,%2,%3},{%4,%5,%6,%7},{%8,%9},{%0,%1,%2,%3};"
                 : "+f"(c[0]), "+f"(c[1]), "+f"(c[2]), "+f"(c[3])
                 : "r"(a[0]), "r"(a[1]), "r"(a[2]), "r"(a[3]), "r"(b[0]), "r"(b[1]));
}

#define CP16(dst, src) asm volatile("cp.async.cg.shared.global [%0],[%1],16;" :: "r"(dst), "l"(src))
#define CPCOMMIT()     asm volatile("cp.async.commit_group;")

// swizzled chunk layout: row stride 32 elems (64B); STS and ldsm conflict-free.
#define SWZ(r, c) (((r) * 32) + ((((c) ^ (((r) >> 1) & 3))) * 8))
#define GW64_SMEM  65536   // 4-stage x (128 A + 128 B) x 32 x 2B
__device__ __forceinline__ float sigf(float x) { return 1.f / (1.f + __expf(-x)); }

// ======================= unified HMMA GEMM: 4 warps, 64x64 warp tile ======
// C(MxN) = A(MxK2,bf16) @ W(NxK2,bf16)^T (+bias) (+P gather epilogue)
// Dual weight: rows >= Msplit use (W2, bias2). Dual idx: rows >= idxSplit use idx2.
__global__ __launch_bounds__(128, 2) void gemm_w64(
    int M, int N, int K2, int wrapA,
    const __nv_bfloat16* __restrict__ A, int lda,
    const __nv_bfloat16* __restrict__ W, int ldw,
    const float* __restrict__ bias,
    const __nv_bfloat16* __restrict__ W2, const float* __restrict__ bias2, int Msplit,
    float* __restrict__ C, int ldc,
    const int* __restrict__ idx, const int* __restrict__ idx2, int idxSplit,
    const float* __restrict__ P, int ldP, int pOff)
{
    extern __shared__ __nv_bfloat16 smw[];
    __nv_bfloat16* Abuf = smw;                    // [4][128*32]
    __nv_bfloat16* Bbuf = smw + 4 * 128 * 32;     // [4][128*32]

    const int m0 = blockIdx.y * 128, n0 = blockIdx.x * 128;
    const __nv_bfloat16* Wp = W;
    const float* bp = bias;
    if (W2 && m0 >= Msplit) { Wp = W2; bp = bias2; }

    const int t = threadIdx.x;
    const int lane = t & 31, warp = t >> 5;
    const int wm = (warp & 1) * 64;
    const int wn = (warp >> 1) * 64;

    float acc[4][8][4];
#pragma unroll
    for (int i = 0; i < 4; i++)
#pragma unroll
        for (int j = 0; j < 8; j++)
#pragma unroll
            for (int k = 0; k < 4; k++) acc[i][j][k] = 0.f;

    const int iters = K2 / 32;

#define PFW(kt, buf)                                                               \
    {                                                                              \
        int kb  = (kt) * 32;                                                       \
        int kbA = (wrapA && kb >= wrapA) ? kb - wrapA : kb;                        \
        _Pragma("unroll")                                                          \
        for (int i = 0; i < 4; i++) {                                              \
            int li = t + i * 128;                                                  \
            int r  = li >> 2;                                                      \
            int c4 = li & 3;                                                       \
            int so = SWZ(r, c4);                                                   \
            CP16(smem_u32(&Abuf[(buf) * 128 * 32 + so]),                           \
                 A + (size_t)(m0 + r) * lda + kbA + c4 * 8);                       \
            CP16(smem_u32(&Bbuf[(buf) * 128 * 32 + so]),                           \
                 Wp + (size_t)(n0 + r) * ldw + kb + c4 * 8);                       \
        }                                                                          \
        CPCOMMIT();                                                                \
    }

    PFW(0, 0);
    if (iters > 1) PFW(1, 1);
    if (iters > 2) PFW(2, 2);

    for (int kt = 0; kt < iters; kt++) {
        int rem = iters - kt;
        if (rem >= 3)      asm volatile("cp.async.wait_group 2;");
        else if (rem == 2) asm volatile("cp.async.wait_group 1;");
        else               asm volatile("cp.async.wait_group 0;");
        __syncthreads();

        if (kt + 3 < iters) PFW(kt + 3, (kt + 3) & 3);

        const __nv_bfloat16* as = Abuf + (kt & 3) * 128 * 32;
        const __nv_bfloat16* ws = Bbuf + (kt & 3) * 128 * 32;
#pragma unroll
        for (int ks = 0; ks < 32; ks += 16) {
            uint32_t af[4][4];
#pragma unroll
            for (int mf = 0; mf < 4; mf++) {
                int arow = wm + mf * 16 + (lane & 15);
                int cidx = (ks >> 3) + (lane >> 4);
                uint32_t ad = smem_u32(&as[SWZ(arow, cidx)]);
                ldsm_x4(af[mf][0], af[mf][1], af[mf][2], af[mf][3], ad);
            }
            uint32_t bfr[8][2];
#pragma unroll
            for (int p = 0; p < 4; p++) {
                int nrow = wn + p * 16 + ((lane >> 4) & 1) * 8 + (lane & 7);
                int cidx = (ks >> 3) + ((lane >> 3) & 1);
                uint32_t ad = smem_u32(&ws[SWZ(nrow, cidx)]);
                uint32_t b0, b1, b2, b3;
                ldsm_x4(b0, b1, b2, b3, ad);
                bfr[p * 2][0] = b0; bfr[p * 2][1] = b1;
                bfr[p * 2 + 1][0] = b2; bfr[p * 2 + 1][1] = b3;
            }
#pragma unroll
            for (int mf = 0; mf < 4; mf++)
#pragma unroll
                for (int nf = 0; nf < 8; nf++)
                    mma16816(acc[mf][nf], af[mf], bfr[nf]);
        }
    }

    // epilogue
#pragma unroll
    for (int mf = 0; mf < 4; mf++) {
#pragma unroll
        for (int half = 0; half < 2; half++) {
            int row = m0 + wm + mf * 16 + (lane >> 2) + half * 8;
            const float* prow = nullptr;
            if (idx) {
                int key = (row < idxSplit) ? idx[row] : idx2[row - idxSplit];
                prow = P + (size_t)key * ldP + pOff;
            }
#pragma unroll
            for (int nf = 0; nf < 8; nf++) {
                int col = n0 + wn + nf * 8 + (lane & 3) * 2;
                float v0 = acc[mf][nf][half * 2 + 0];
                float v1 = acc[mf][nf][half * 2 + 1];
                if (bp)   { v0 += bp[col];   v1 += bp[col + 1]; }
                if (prow) { v0 += prow[col]; v1 += prow[col + 1]; }
                float2 o; o.x = v0; o.y = v1;
                *(float2*)(C + (size_t)row * ldc + col) = o;
            }
        }
    }
}

static inline void mgemm(int M, int N, int K2, int wrapA,
                         const __nv_bfloat16* A, int lda,
                         const __nv_bfloat16* W, int ldw, const float* bias,
                         float* C, int ldc,
                         const int* idx = nullptr, const float* P = nullptr,
                         int ldP = 0, int pOff = 0,
                         const __nv_bfloat16* W2 = nullptr, const float* b2 = nullptr,
                         int Msplit = 0,
                         const int* idx2 = nullptr, int idxSplit = 0x7fffffff)
{
    dim3 g(N / 128, M / 128);
    gemm_w64<<<g, 128, GW64_SMEM>>>(M, N, K2, wrapA, A, lda, W, ldw, bias,
                                    W2, b2, Msplit, C, ldc, idx, idx2, idxSplit,
                                    P, ldP, pOff);
}

// ---------------- key GRU gates: 4 ch/thread, 4 rows/block ----------------
__global__ __launch_bounds__(256) void key_gates_kernel(
    const int* __restrict__ keys_c, const int* __restrict__ keys_r, int t)
{
    int dir = blockIdx.y;
    int n   = blockIdx.x * 4 + (threadIdx.x >> 6);   // row 0..10239
    int c4  = (threadIdx.x & 63) * 4;                // channel base
    int te  = (dir == 0) ? t : (KK_ - 1 - t);
    int key = (n < BS_) ? keys_c[n * KK_ + te] : keys_r[(n - BS_) * KK_ + te];

    const float* gi = g_P + (size_t)key * 3072 + dir * 768;
    const float* gh = g_gh + (size_t)dir * NKEY_ * G3_ + (size_t)n * G3_;
    __nv_bfloat16* h2 = g_h2 + (size_t)(dir * NKEY_ + n) * 512;

    float4 ghr = *(const float4*)(gh + c4);
    float4 ghz = *(const float4*)(gh + 256 + c4);
    float4 ghn = *(const float4*)(gh + 512 + c4);
    float4 gir = *(const float4*)(gi + c4);
    float4 giz = *(const float4*)(gi + 256 + c4);
    float4 gin = *(const float4*)(gi + 512 + c4);
    __nv_bfloat162 hhi2[2], hlo2[2];
    *(uint2*)hhi2 = *(const uint2*)(h2 + c4);
    *(uint2*)hlo2 = *(const uint2*)(h2 + 256 + c4);

    float hr[4] = {ghr.x, ghr.y, ghr.z, ghr.w};
    float hz[4] = {ghz.x, ghz.y, ghz.z, ghz.w};
    float hn[4] = {ghn.x, ghn.y, ghn.z, ghn.w};
    float ir[4] = {gir.x, gir.y, gir.z, gir.w};
    float iz[4] = {giz.x, giz.y, giz.z, giz.w};
    float in_[4] = {gin.x, gin.y, gin.z, gin.w};
    float hp[4];
    hp[0] = __bfloat162float(hhi2[0].x) + __bfloat162float(hlo2[0].x);
    hp[1] = __bfloat162float(hhi2[0].y) + __bfloat162float(hlo2[0].y);
    hp[2] = __bfloat162float(hhi2[1].x) + __bfloat162float(hlo2[1].x);
    hp[3] = __bfloat162float(hhi2[1].y) + __bfloat162float(hlo2[1].y);

    __nv_bfloat16 ohi[4], olo[4];
#pragma unroll
    for (int j = 0; j < 4; j++) {
        float r  = sigf(ir[j] + hr[j]);
        float z  = sigf(iz[j] + hz[j]);
        float nn = tanhf(in_[j] + r * hn[j]);
        float hv = (1.f - z) * nn + z * hp[j];
        ohi[j] = __float2bfloat16(hv);
        olo[j] = __float2bfloat16(hv - __bfloat162float(ohi[j]));
    }
    *(uint2*)(h2 + c4)       = *(uint2*)ohi;
    *(uint2*)(h2 + 256 + c4) = *(uint2*)olo;
}

// ---------------- t=0 key gates (h=0, gh=bias) ----------------
__global__ void key_gates0_kernel(const int* __restrict__ keys_c,
                                  const int* __restrict__ keys_r,
                                  const float* __restrict__ bhf,
                                  const float* __restrict__ bhb)
{
    int n   = blockIdx.x;
    int c   = threadIdx.x;
    int dir = blockIdx.y;
    int te  = (dir == 0) ? 0 : (KK_ - 1);
    int key = (n < BS_) ? keys_c[n * KK_ + te] : keys_r[(n - BS_) * KK_ + te];

    const float* gi = g_P + (size_t)key * 3072 + dir * 768;
    const float* bb = dir ? bhb : bhf;
    float ir = gi[c], iz = gi[256 + c], in = gi[512 + c];
    float r  = sigf(ir + bb[c]);
    float z  = sigf(iz + bb[256 + c]);
    float nn = tanhf(in + r * bb[512 + c]);
    float hv = (1.f - z) * nn;

    __nv_bfloat16 hi = __float2bfloat16(hv);
    __nv_bfloat16 lo = __float2bfloat16(hv - __bfloat162float(hi));
    __nv_bfloat16* h2 = g_h2 + (size_t)(dir * NKEY_ + n) * 512;
    h2[c] = hi; h2[256 + c] = lo;
}

__global__ void ksum2_kernel()
{
    int i = blockIdx.x * blockDim.x + threadIdx.x;
    if (i >= NKEY_ * H_) return;
    int n = i >> 8, c = i & 255;
    const __nv_bfloat16* hf = g_h2 + (size_t)n * 512;
    const __nv_bfloat16* hb = g_h2 + (size_t)(NKEY_ + n) * 512;
    float s = __bfloat162float(hf[c]) + __bfloat162float(hf[256 + c])
            + __bfloat162float(hb[c]) + __bfloat162float(hb[256 + c]);
    __nv_bfloat16 hi = __float2bfloat16(s);
    __nv_bfloat16 lo = __float2bfloat16(s - __bfloat162float(hi));
    __nv_bfloat16* y = g_ksum2 + (size_t)n * 512;
    y[c] = hi; y[256 + c] = lo;
}

// ---------------- unified prep: zeros + splits + bias concat ----------------
__global__ void prep_kernel(const float* __restrict__ emb,
                            const float* kWif, const float* kWib,
                            const float* eWif, const float* eWib,
                            const float* kWhf, const float* kWhb,
                            const float* kbif, const float* kbib,
                            const float* ebif, const float* ebib)
{
    const int N_EH  = 4 * B_ * H_;
    const int N_EMB = V_ * 320;
    const int SZP = 768 * 320, SZH = 768 * 256;
    const int N_W = 4 * SZP + 4 * SZH;
    const int total = N_EH + N_EMB + N_W + 3072;

    for (int i = blockIdx.x * blockDim.x + threadIdx.x; i < total;
         i += gridDim.x * blockDim.x) {
        int j = i;
        if (j < N_EH) { g_eh[j] = 0.f; continue; }
        j -= N_EH;
        if (j < N_EMB) {
            int r = j / 320, c = j - r * 320;
            float x = (c < 300) ? emb[(size_t)r * 300 + c] : 0.f;
            __nv_bfloat16 hi = __float2bfloat16(x);
            __nv_bfloat16 lo = __float2bfloat16(x - __bfloat162float(hi));
            __nv_bfloat16* y = g_emb2 + (size_t)r * 640;
            y[c] = hi; y[320 + c] = lo;
            continue;
        }
        j -= N_EMB;
        if (j < N_W) {
            if (j < 4 * SZP) {
                int seg = j / SZP, loc = j - seg * SZP;
                const int Kpad = 320, Cc = 300;
                const float* srcs[4] = {kWif, kWib, eWif, eWib};
                int lds[4] = {300, 300, 556, 556};
                const float* X = srcs[seg]; int ldx = lds[seg];
                __nv_bfloat16* Y = g_Wpre2 + (size_t)seg * 768 * 960;
                int r = loc / Kpad, c = loc - r * Kpad;
                float x = (c < Cc) ? X[(size_t)r * ldx + c] : 0.f;
                __nv_bfloat16 hi = __float2bfloat16(x);
                __nv_bfloat16 lo = __float2bfloat16(x - __bfloat162float(hi));
                __nv_bfloat16* y = Y + (size_t)r * 3 * Kpad;
                y[c] = hi; y[Kpad + c] = hi; y[2 * Kpad + c] = lo;
            } else {
                int jj = j - 4 * SZP;
                int seg = jj / SZH, loc = jj - seg * SZH;
                const int Kpad = 256;
                int r = loc / Kpad, c = loc - r * Kpad;
                const float* X; int ldx; __nv_bfloat16* Y;
                if (seg < 2) { X = seg ? kWhb : kWhf; ldx = 256;
                               Y = g_Whk2 + (size_t)seg * 768 * 768; }
                else         { X = (seg == 2) ? (eWif + 300) : (eWib + 300); ldx = 556;
                               Y = g_eW2 + (size_t)(seg - 2) * 768 * 768; }
                float x = X[(size_t)r * ldx + c];
                __nv_bfloat16 hi = __float2bfloat16(x);
                __nv_bfloat16 lo = __float2bfloat16(x - __bfloat162float(hi));
                __nv_bfloat16* y = Y + (size_t)r * 3 * Kpad;
                y[c] = hi; y[Kpad + c] = hi; y[2 * Kpad + c] = lo;
            }
            continue;
        }
        j -= N_W;
        float v;
        if      (j < 768)  v = kbif[j];
        else if (j < 1536) v = kbib[j - 768];
        else if (j < 2304) v = ebif[j - 1536];
        else               v = ebib[j - 2304];
        g_bcat[j] = v;
    }
}

// ---------------- persistent encoder BiGRU (per-stream barriers) ----------
__device__ __forceinline__ void gridbar_st(int st)
{
    __syncthreads();
    if (threadIdx.x == 0) {
        __threadfence();
        unsigned prev = atomicAdd(&g_barCnt4[st], 1u);
        unsigned target = (prev / 32u + 1u) * 32u;
        while (*(volatile unsigned*)&g_barCnt4[st] < target) { }
    }
    __syncthreads();
}

__global__ __launch_bounds__(256, 1) void enc_persistent_kernel(
    const float* __restrict__ Whf, const float* __restrict__ Whb,
    const float* __restrict__ bhf, const float* __restrict__ bhb)
{
    __shared__ float Hs[32][260];
    __shared__ float Wsh[24][260];
    __shared__ float bsh[24];

    const int t    = threadIdx.x;
    const int b    = blockIdx.x;
    const int st   = b & 3;
    const int c0   = (b >> 2) * 8;
    const float* Wh = (st & 1) ? Whb : Whf;
    const float* bh = (st & 1) ? bhb : bhf;
    const float* gix = g_gix + (size_t)(st >> 1) * BS_ * 1536;
    const int gbase = (st & 1) * 768;
    float* ehp = g_eh + st * B_ * H_;

    for (int li = t; li < 24 * 64; li += 256) {
        int r = li >> 6, kq = (li & 63) * 4;
        int wrow = (r >> 3) * 256 + c0 + (r & 7);
        *(float4*)&Wsh[r][kq] = *(const float4*)(Wh + (size_t)wrow * H_ + kq);
    }
    if (t < 24) bsh[t] = bh[(t >> 3) * 256 + c0 + (t & 7)];
    __syncthreads();

    const int lane = t & 31;
    const int warp = t >> 5;
    const int ch = c0 + warp;

    for (int step = 0; step < S_; step++) {
        for (int li = t; li < 32 * 64; li += 256) {
            int r = li >> 6, kq = (li & 63) * 4;
            float4 v = __ldcg((const float4*)(ehp + r * H_ + kq));
            *(float4*)&Hs[r][kq] = v;
        }
        __syncthreads();

        float accR = 0.f, accZ = 0.f, accN = 0.f;
#pragma unroll 8
        for (int k = 0; k < 64; k++) {
            float4 hv = *(const float4*)&Hs[lane][k * 4];
            float4 wr = *(const float4*)&Wsh[warp][k * 4];
            float4 wz = *(const float4*)&Wsh[8 + warp][k * 4];
            float4 wn = *(const float4*)&Wsh[16 + warp][k * 4];
            accR += hv.x*wr.x + hv.y*wr.y + hv.z*wr.z + hv.w*wr.w;
            accZ += hv.x*wz.x + hv.y*wz.y + hv.z*wz.z + hv.w*wz.w;
            accN += hv.x*wn.x + hv.y*wn.y + hv.z*wn.z + hv.w*wn.w;
        }

        int s   = (st & 1) ? (S_ - 1 - step) : step;
        int row = lane * S_ + s;
        const float* gi = gix + (size_t)row * 1536 + gbase;
        float ir = gi[ch], iz = gi[256 + ch], in = gi[512 + ch];
        float r  = sigf(ir + accR + bsh[warp]);
        float z  = sigf(iz + accZ + bsh[8 + warp]);
        float nn = tanhf(in + r * (accN + bsh[16 + warp]));
        float hv = (1.f - z) * nn + z * Hs[lane][ch];
        ehp[lane * H_ + ch] = hv;
        if (st == 0)      g_sc[(size_t)row * 512 + ch]       = hv;
        else if (st == 1) g_sc[(size_t)row * 512 + 256 + ch] = hv;

        gridbar_st(st);
    }
}

__global__ void rcopy_kernel()
{
    int i = blockIdx.x * blockDim.x + threadIdx.x;
    int b = i >> 9, c = i & 511;
    g_r[i] = (c < 256) ? g_eh[2 * B_ * H_ + b * 256 + c]
                       : g_eh[3 * B_ * H_ + b * 256 + (c - 256)];
}

// ---------------- SIMT GEMM for attention ----------------
__global__ __launch_bounds__(256) void gemm_sm(
    int M, int N, int K,
    const float* __restrict__ A, int lda,
    const float* __restrict__ W, int ldw,
    const float* __restrict__ bias,
    float* __restrict__ C, int ldc)
{
    __shared__ float Asx[16][128];
    __shared__ float Wsx[16][64];

    const int m0 = blockIdx.y * 128;
    const int n0 = blockIdx.x * 64;
    const int t  = threadIdx.x;
    const int tx = t & 15;
    const int ty = t >> 4;

    float acc[8][4];
#pragma unroll
    for (int i = 0; i < 8; i++)
#pragma unroll
        for (int j = 0; j < 4; j++) acc[i][j] = 0.f;

    for (int k0 = 0; k0 < K; k0 += 16) {
#pragma unroll
        for (int i = 0; i < 2; i++) {
            int li  = t + i * 256;
            int row = li >> 2;
            int kq  = (li & 3) * 4;
            float4 v = *(const float4*)(A + (size_t)(m0 + row) * lda + k0 + kq);
            Asx[kq + 0][row] = v.x; Asx[kq + 1][row] = v.y;
            Asx[kq + 2][row] = v.z; Asx[kq + 3][row] = v.w;
        }
        {
            int row = t >> 2;
            int kq  = (t & 3) * 4;
            float4 v = *(const float4*)(W + (size_t)(n0 + row) * ldw + k0 + kq);
            Wsx[kq + 0][row] = v.x; Wsx[kq + 1][row] = v.y;
            Wsx[kq + 2][row] = v.z; Wsx[kq + 3][row] = v.w;
        }
        __syncthreads();
#pragma unroll
        for (int kk = 0; kk < 16; kk++) {
            float4 a0 = *(const float4*)&Asx[kk][ty * 8];
            float4 a1 = *(const float4*)&Asx[kk][ty * 8 + 4];
            float4 w  = *(const float4*)&Wsx[kk][tx * 4];
            float av[8] = {a0.x, a0.y, a0.z, a0.w, a1.x, a1.y, a1.z, a1.w};
            float wv[4] = {w.x, w.y, w.z, w.w};
#pragma unroll
            for (int i = 0; i < 8; i++)
#pragma unroll
                for (int j = 0; j < 4; j++) acc[i][j] += av[i] * wv[j];
        }
        __syncthreads();
    }

#pragma unroll
    for (int i = 0; i < 8; i++) {
        int row = m0 + ty * 8 + i;
        float4 o;
        o.x = acc[i][0] + bias[n0 + tx * 4 + 0];
        o.y = acc[i][1] + bias[n0 + tx * 4 + 1];
        o.z = acc[i][2] + bias[n0 + tx * 4 + 2];
        o.w = acc[i][3] + bias[n0 + tx * 4 + 3];
        *(float4*)(C + (size_t)row * ldc + n0 + tx * 4) = o;
    }
}

// ---------------- attention tail ----------------
__device__ __forceinline__ float blockReduceSum(float v)
{
    __shared__ float sh[32];
    for (int o = 16; o; o >>= 1) v += __shfl_down_sync(0xffffffffu, v, o);
    int lane = threadIdx.x & 31, w = threadIdx.x >> 5;
    if (lane == 0) sh[w] = v;
    __syncthreads();
    int nw = (blockDim.x + 31) >> 5;
    v = (w == 0 && lane < nw) ? sh[lane] : 0.f;
    if (w == 0)
        for (int o = 16; o; o >>= 1) v += __shfl_down_sync(0xffffffffu, v, o);
    return v;
}

__global__ void energy_kernel()
{
    int bs = blockIdx.x;
    int b  = bs / S_;
    float p = 0.f;
    for (int k = threadIdx.x; k < 512; k += 128)
        p += g_a[(size_t)bs * 512 + k] * g_r[b * 512 + k];
    float s = blockReduceSum(p);
    if (threadIdx.x == 0) g_energy[bs] = s;
}

__global__ void softmax_kernel(const float* __restrict__ mask)
{
    int b = blockIdx.x;
    __shared__ float ex[S_];
    __shared__ float smx, ssum;
    int tid = threadIdx.x;
    if (tid < S_) ex[tid] = g_energy[b * S_ + tid];
    __syncthreads();
    if (tid == 0) { float m = -1e30f; for (int s = 0; s < S_; s++) m = fmaxf(m, ex[s]); smx = m; }
    __syncthreads();
    if (tid < S_) ex[tid] = __expf(ex[tid] - smx);
    __syncthreads();
    if (tid == 0) { float s = 0.f; for (int i = 0; i < S_; i++) s += ex[i]; ssum = s; }
    __syncthreads();
    if (tid < S_) g_alpha[b * S_ + tid] = ex[tid] / ssum * mask[b * S_ + tid];
}

__global__ void cattn_kernel()
{
    int b = blockIdx.x, d = threadIdx.x;
    float acc = 0.f;
    for (int s = 0; s < S_; s++)
        acc += g_alpha[b * S_ + s] * g_sc[(size_t)(b * S_ + s) * 512 + d];
    g_cattn[b * 512 + d] = acc;
}

__global__ void final_kernel(const float* __restrict__ Mm,
                             const float* __restrict__ b0,
                             float* __restrict__ out)
{
    int b = blockIdx.x;
    float part = 0.f;
    for (int d = threadIdx.x; d < 512; d += 256) {
        const float* mr = Mm + (size_t)d * 512;
        const float* rr = g_r + b * 512;
        float td = 0.f;
        for (int e = 0; e < 512; e++) td += mr[e] * rr[e];
        part += g_cattn[b * 512 + d] * td;
    }
    float s = blockReduceSum(part);
    if (threadIdx.x == 0) out[b] = s + b0[0];
}

// ---------------- host orchestration ----------------
extern "C" void kernel_launch(void* const* d_in, const int* in_sizes, int n_in,
                              void* d_out, int out_size)
{
    const int*   x1     = (const int*)d_in[0];
    const int*   x2     = (const int*)d_in[1];
    const int*   keys_c = (const int*)d_in[2];
    const int*   keys_r = (const int*)d_in[3];
    const float* x1mask = (const float*)d_in[4];
    const float* emb    = (const float*)d_in[5];
    const float* kWif   = (const float*)d_in[6];
    const float* kWhf   = (const float*)d_in[7];
    const float* kbif   = (const float*)d_in[8];
    const float* kbhf   = (const float*)d_in[9];
    const float* kWib   = (const float*)d_in[10];
    const float* kWhb   = (const float*)d_in[11];
    const float* kbib   = (const float*)d_in[12];
    const float* kbhb   = (const float*)d_in[13];
    const float* eWif   = (const float*)d_in[14];
    const float* eWhf   = (const float*)d_in[15];
    const float* ebif   = (const float*)d_in[16];
    const float* ebhf   = (const float*)d_in[17];
    const float* eWib   = (const float*)d_in[18];
    const float* eWhb   = (const float*)d_in[19];
    const float* ebib   = (const float*)d_in[20];
    const float* ebhb   = (const float*)d_in[21];
    const float* attn_W = (const float*)d_in[22];
    const float* attn_b = (const float*)d_in[23];
    const float* Mm     = (const float*)d_in[24];
    const float* b0     = (const float*)d_in[25];
    float* out = (float*)d_out;

    float *pP, *pBcat, *pGix, *pSc, *pA, *pGH;
    __nv_bfloat16 *pEmb2, *pWpre2, *pWhk2, *pEW2, *pH2, *pKsum2;
    cudaGetSymbolAddress((void**)&pP,     g_P);
    cudaGetSymbolAddress((void**)&pBcat,  g_bcat);
    cudaGetSymbolAddress((void**)&pGix,   g_gix);
    cudaGetSymbolAddress((void**)&pSc,    g_sc);
    cudaGetSymbolAddress((void**)&pA,     g_a);
    cudaGetSymbolAddress((void**)&pGH,    g_gh);
    cudaGetSymbolAddress((void**)&pEmb2,  g_emb2);
    cudaGetSymbolAddress((void**)&pWpre2, g_Wpre2);
    cudaGetSymbolAddress((void**)&pWhk2,  g_Whk2);
    cudaGetSymbolAddress((void**)&pEW2,   g_eW2);
    cudaGetSymbolAddress((void**)&pH2,    g_h2);
    cudaGetSymbolAddress((void**)&pKsum2, g_ksum2);

    cudaFuncSetAttribute(gemm_w64, cudaFuncAttributeMaxDynamicSharedMemorySize,
                         GW64_SMEM);

    // 0: unified prep (zeros + bf16 splits + bias concat)
    prep_kernel<<<8192, 256>>>(emb, kWif, kWib, eWif, eWib, kWhf, kWhb,
                               kbif, kbib, ebif, ebib);

    // 1: unified precompute GEMM  g_P = emb2 @ [kWif;kWib;eWif;eWib]^T + bcat
    mgemm(V_, 3072, 960, 640, pEmb2, 640, pWpre2, 960, pBcat, pP, 3072);

    // 2: key BiGRU t=0 (h=0 -> gh=bias)
    key_gates0_kernel<<<dim3(NKEY_, 2), 256>>>(keys_c, keys_r, kbhf, kbhb);

    // 3..: key steps: dual-weight HMMA GEMM + vectorized gates
    for (int t = 1; t < KK_; t++) {
        mgemm(2 * NKEY_, G3_, 768, 512, pH2, 512, pWhk2, 768, kbhf, pGH, G3_,
              nullptr, nullptr, 0, 0, pWhk2 + 768 * 768, kbhb, NKEY_);
        key_gates_kernel<<<dim3(NKEY_ / 4, 2), 256>>>(keys_c, keys_r, t);
    }

    ksum2_kernel<<<(NKEY_ * H_ + 255) / 256, 256>>>();

    // encoder input projections: ONE merged GEMM (x1 rows then x2 rows)
    mgemm(NKEY_, 1536, 768, 512, pKsum2, 512, pEW2, 768, nullptr,
          pGix, 1536, x1, pP, 3072, 1536,
          nullptr, nullptr, 0, x2, BS_);

    // encoder BiGRU: persistent, per-stream barriers
    enc_persistent_kernel<<<128, 256>>>(eWhf, eWhb, ebhf, ebhb);
    rcopy_kernel<<<64, 256>>>();

    // attention + output
    {
        dim3 g(512 / 64, BS_ / 128);
        gemm_sm<<<g, 256>>>(BS_, 512, 512, pSc, 512, attn_W, 512, attn_b, pA, 512);
    }
    energy_kernel<<<BS_, 128>>>();
    softmax_kernel<<<B_, 192>>>(x1mask);
    cattn_kernel<<<B_, 512>>>();
    final_kernel<<<B_, 256>>>(Mm, b0, out);
}

// round 15
// speedup vs baseline: 2.1782x; 1.1078x over previous
#include <cuda_runtime.h>
#include <cuda_bf16.h>
#include <math.h>
#include <stdint.h>

// ---------------- problem constants ----------------
#define B_    32
#define S_    160
#define KK_   44
#define E_    300
#define H_    256
#define V_    32000
#define G3_   768          // 3*H
#define NKEY_ 10240        // 2*B*S (keys_c ++ keys_r)
#define BS_   5120         // B*S

// ---------------- device scratch (static, no allocs) ----------------
__device__ float g_P    [V_ * 3072];
__device__ float g_bcat [3072];
__device__ __nv_bfloat16 g_emb2 [V_ * 640];       // emb split [hi|lo], Kpad=320 (wrapA)
__device__ __nv_bfloat16 g_Wpre2[4 * 768 * 960];  // kWif,kWib,eWif,eWib [hi|hi|lo]
__device__ __nv_bfloat16 g_Whk2 [2 * 768 * 768];  // kWhf,kWhb [hi|hi|lo]
__device__ __nv_bfloat16 g_eW2  [2 * 768 * 768];  // eWif[:,300:],eWib[:,300:] [hi|hi|lo]
__device__ __nv_bfloat16 g_h2 [2 * NKEY_ * 512];  // key GRU hidden split [hi|lo] (wrapA)
__device__ float g_gh   [2 * NKEY_ * G3_];        // key GRU gh temp
__device__ __nv_bfloat16 g_ksum2[NKEY_ * 512];    // (hf+hb) split [hi|lo]
__device__ float g_gix  [2 * BS_ * 1536];         // enc input proj
__device__ float g_eh   [4 * B_ * H_];
__device__ float g_sc   [BS_ * 512];
__device__ float g_a    [BS_ * 512];
__device__ float g_energy[BS_];
__device__ float g_alpha [BS_];
__device__ float g_r    [B_ * 512];
__device__ float g_cattn[B_ * 512];
__device__ unsigned g_barCnt4[4];                 // encoder per-stream barriers

// ======================= PTX helpers ==============================
__device__ __forceinline__ uint32_t smem_u32(const void* p)
{
    return (uint32_t)__cvta_generic_to_shared(p);
}

__device__ __forceinline__ void ldsm_x4(uint32_t& r0, uint32_t& r1,
                                        uint32_t& r2, uint32_t& r3, uint32_t addr)
{
    asm volatile("ldmatrix.sync.aligned.m8n8.x4.shared.b16 {%0,%1,%2,%3},[%4];"
                 : "=r"(r0), "=r"(r1), "=r"(r2), "=r"(r3) : "r"(addr));
}

__device__ __forceinline__ void mma16816(float* c, const uint32_t* a, const uint32_t* b)
{
    asm volatile("mma.sync.aligned.m16n8k16.row.col.f32.bf16.bf16.f32 "
                 "{%0,%1,%2,%3},{%4,%5,%6,%7},{%8,%9},{%0,%1,%2,%3};"
                 : "+f"(c[0]), "+f"(c[1]), "+f"(c[2]), "+f"(c[3])
                 : "r"(a[0]), "r"(a[1]), "r"(a[2]), "r"(a[3]), "r"(b[0]), "r"(b[1]));
}

#define CP16(dst, src) asm volatile("cp.async.cg.shared.global [%0],[%1],16;" :: "r"(dst), "l"(src))
#define CPCOMMIT()     asm volatile("cp.async.commit_group;")

// swizzled chunk layout: row stride 32 elems (64B); STS and ldsm conflict-free.
#define SWZ(r, c) (((r) * 32) + ((((c) ^ (((r) >> 1) & 3))) * 8))
#define GW64_SMEM  65536   // 4-stage x (128 A + 128 B) x 32 x 2B
__device__ __forceinline__ float sigf(float x) { return 1.f / (1.f + __expf(-x)); }

// ======================= unified HMMA GEMM: 4 warps, 64x64 warp tile ======
// C(MxN) = A(MxK2,bf16) @ W(NxK2,bf16)^T (+bias) (+P gather epilogue)
// Dual weight: rows >= Msplit use (W2, bias2). Dual idx: rows >= idxSplit use idx2.
__global__ __launch_bounds__(128, 2) void gemm_w64(
    int M, int N, int K2, int wrapA,
    const __nv_bfloat16* __restrict__ A, int lda,
    const __nv_bfloat16* __restrict__ W, int ldw,
    const float* __restrict__ bias,
    const __nv_bfloat16* __restrict__ W2, const float* __restrict__ bias2, int Msplit,
    float* __restrict__ C, int ldc,
    const int* __restrict__ idx, const int* __restrict__ idx2, int idxSplit,
    const float* __restrict__ P, int ldP, int pOff)
{
    extern __shared__ __nv_bfloat16 smw[];
    __nv_bfloat16* Abuf = smw;                    // [4][128*32]
    __nv_bfloat16* Bbuf = smw + 4 * 128 * 32;     // [4][128*32]

    const int m0 = blockIdx.y * 128, n0 = blockIdx.x * 128;
    const __nv_bfloat16* Wp = W;
    const float* bp = bias;
    if (W2 && m0 >= Msplit) { Wp = W2; bp = bias2; }

    const int t = threadIdx.x;
    const int lane = t & 31, warp = t >> 5;
    const int wm = (warp & 1) * 64;
    const int wn = (warp >> 1) * 64;

    float acc[4][8][4];
#pragma unroll
    for (int i = 0; i < 4; i++)
#pragma unroll
        for (int j = 0; j < 8; j++)
#pragma unroll
            for (int k = 0; k < 4; k++) acc[i][j][k] = 0.f;

    const int iters = K2 / 32;

#define PFW(kt, buf)                                                               \
    {                                                                              \
        int kb  = (kt) * 32;                                                       \
        int kbA = (wrapA && kb >= wrapA) ? kb - wrapA : kb;                        \
        _Pragma("unroll")                                                          \
        for (int i = 0; i < 4; i++) {                                              \
            int li = t + i * 128;                                                  \
            int r  = li >> 2;                                                      \
            int c4 = li & 3;                                                       \
            int so = SWZ(r, c4);                                                   \
            CP16(smem_u32(&Abuf[(buf) * 128 * 32 + so]),                           \
                 A + (size_t)(m0 + r) * lda + kbA + c4 * 8);                       \
            CP16(smem_u32(&Bbuf[(buf) * 128 * 32 + so]),                           \
                 Wp + (size_t)(n0 + r) * ldw + kb + c4 * 8);                       \
        }                                                                          \
        CPCOMMIT();                                                                \
    }

    PFW(0, 0);
    if (iters > 1) PFW(1, 1);
    if (iters > 2) PFW(2, 2);

    for (int kt = 0; kt < iters; kt++) {
        int rem = iters - kt;
        if (rem >= 3)      asm volatile("cp.async.wait_group 2;");
        else if (rem == 2) asm volatile("cp.async.wait_group 1;");
        else               asm volatile("cp.async.wait_group 0;");
        __syncthreads();

        if (kt + 3 < iters) PFW(kt + 3, (kt + 3) & 3);

        const __nv_bfloat16* as = Abuf + (kt & 3) * 128 * 32;
        const __nv_bfloat16* ws = Bbuf + (kt & 3) * 128 * 32;
#pragma unroll
        for (int ks = 0; ks < 32; ks += 16) {
            uint32_t af[4][4];
#pragma unroll
            for (int mf = 0; mf < 4; mf++) {
                int arow = wm + mf * 16 + (lane & 15);
                int cidx = (ks >> 3) + (lane >> 4);
                uint32_t ad = smem_u32(&as[SWZ(arow, cidx)]);
                ldsm_x4(af[mf][0], af[mf][1], af[mf][2], af[mf][3], ad);
            }
            uint32_t bfr[8][2];
#pragma unroll
            for (int p = 0; p < 4; p++) {
                int nrow = wn + p * 16 + ((lane >> 4) & 1) * 8 + (lane & 7);
                int cidx = (ks >> 3) + ((lane >> 3) & 1);
                uint32_t ad = smem_u32(&ws[SWZ(nrow, cidx)]);
                uint32_t b0, b1, b2, b3;
                ldsm_x4(b0, b1, b2, b3, ad);
                bfr[p * 2][0] = b0; bfr[p * 2][1] = b1;
                bfr[p * 2 + 1][0] = b2; bfr[p * 2 + 1][1] = b3;
            }
#pragma unroll
            for (int mf = 0; mf < 4; mf++)
#pragma unroll
                for (int nf = 0; nf < 8; nf++)
                    mma16816(acc[mf][nf], af[mf], bfr[nf]);
        }
    }

    // epilogue
#pragma unroll
    for (int mf = 0; mf < 4; mf++) {
#pragma unroll
        for (int half = 0; half < 2; half++) {
            int row = m0 + wm + mf * 16 + (lane >> 2) + half * 8;
            const float* prow = nullptr;
            if (idx) {
                int key = (row < idxSplit) ? idx[row] : idx2[row - idxSplit];
                prow = P + (size_t)key * ldP + pOff;
            }
#pragma unroll
            for (int nf = 0; nf < 8; nf++) {
                int col = n0 + wn + nf * 8 + (lane & 3) * 2;
                float v0 = acc[mf][nf][half * 2 + 0];
                float v1 = acc[mf][nf][half * 2 + 1];
                if (bp)   { v0 += bp[col];   v1 += bp[col + 1]; }
                if (prow) { v0 += prow[col]; v1 += prow[col + 1]; }
                float2 o; o.x = v0; o.y = v1;
                *(float2*)(C + (size_t)row * ldc + col) = o;
            }
        }
    }
}

static inline void mgemm(int M, int N, int K2, int wrapA,
                         const __nv_bfloat16* A, int lda,
                         const __nv_bfloat16* W, int ldw, const float* bias,
                         float* C, int ldc,
                         const int* idx = nullptr, const float* P = nullptr,
                         int ldP = 0, int pOff = 0,
                         const __nv_bfloat16* W2 = nullptr, const float* b2 = nullptr,
                         int Msplit = 0,
                         const int* idx2 = nullptr, int idxSplit = 0x7fffffff,
                         cudaStream_t st = 0)
{
    dim3 g(N / 128, M / 128);
    gemm_w64<<<g, 128, GW64_SMEM, st>>>(M, N, K2, wrapA, A, lda, W, ldw, bias,
                                        W2, b2, Msplit, C, ldc, idx, idx2, idxSplit,
                                        P, ldP, pOff);
}

// ---------------- key GRU gates: 4 ch/thread, 4 rows/block, one dir ------
__global__ __launch_bounds__(256) void key_gates_kernel(
    const int* __restrict__ keys_c, const int* __restrict__ keys_r, int t, int dir)
{
    int n   = blockIdx.x * 4 + (threadIdx.x >> 6);   // row 0..10239
    int c4  = (threadIdx.x & 63) * 4;                // channel base
    int te  = (dir == 0) ? t : (KK_ - 1 - t);
    int key = (n < BS_) ? keys_c[n * KK_ + te] : keys_r[(n - BS_) * KK_ + te];

    const float* gi = g_P + (size_t)key * 3072 + dir * 768;
    const float* gh = g_gh + (size_t)dir * NKEY_ * G3_ + (size_t)n * G3_;
    __nv_bfloat16* h2 = g_h2 + (size_t)(dir * NKEY_ + n) * 512;

    float4 ghr = *(const float4*)(gh + c4);
    float4 ghz = *(const float4*)(gh + 256 + c4);
    float4 ghn = *(const float4*)(gh + 512 + c4);
    float4 gir = *(const float4*)(gi + c4);
    float4 giz = *(const float4*)(gi + 256 + c4);
    float4 gin = *(const float4*)(gi + 512 + c4);
    __nv_bfloat162 hhi2[2], hlo2[2];
    *(uint2*)hhi2 = *(const uint2*)(h2 + c4);
    *(uint2*)hlo2 = *(const uint2*)(h2 + 256 + c4);

    float hr[4] = {ghr.x, ghr.y, ghr.z, ghr.w};
    float hz[4] = {ghz.x, ghz.y, ghz.z, ghz.w};
    float hn[4] = {ghn.x, ghn.y, ghn.z, ghn.w};
    float ir[4] = {gir.x, gir.y, gir.z, gir.w};
    float iz[4] = {giz.x, giz.y, giz.z, giz.w};
    float in_[4] = {gin.x, gin.y, gin.z, gin.w};
    float hp[4];
    hp[0] = __bfloat162float(hhi2[0].x) + __bfloat162float(hlo2[0].x);
    hp[1] = __bfloat162float(hhi2[0].y) + __bfloat162float(hlo2[0].y);
    hp[2] = __bfloat162float(hhi2[1].x) + __bfloat162float(hlo2[1].x);
    hp[3] = __bfloat162float(hhi2[1].y) + __bfloat162float(hlo2[1].y);

    __nv_bfloat16 ohi[4], olo[4];
#pragma unroll
    for (int j = 0; j < 4; j++) {
        float r  = sigf(ir[j] + hr[j]);
        float z  = sigf(iz[j] + hz[j]);
        float nn = tanhf(in_[j] + r * hn[j]);
        float hv = (1.f - z) * nn + z * hp[j];
        ohi[j] = __float2bfloat16(hv);
        olo[j] = __float2bfloat16(hv - __bfloat162float(ohi[j]));
    }
    *(uint2*)(h2 + c4)       = *(uint2*)ohi;
    *(uint2*)(h2 + 256 + c4) = *(uint2*)olo;
}

// ---------------- t=0 key gates (h=0, gh=bias) ----------------
__global__ void key_gates0_kernel(const int* __restrict__ keys_c,
                                  const int* __restrict__ keys_r,
                                  const float* __restrict__ bhf,
                                  const float* __restrict__ bhb)
{
    int n   = blockIdx.x;
    int c   = threadIdx.x;
    int dir = blockIdx.y;
    int te  = (dir == 0) ? 0 : (KK_ - 1);
    int key = (n < BS_) ? keys_c[n * KK_ + te] : keys_r[(n - BS_) * KK_ + te];

    const float* gi = g_P + (size_t)key * 3072 + dir * 768;
    const float* bb = dir ? bhb : bhf;
    float ir = gi[c], iz = gi[256 + c], in = gi[512 + c];
    float r  = sigf(ir + bb[c]);
    float z  = sigf(iz + bb[256 + c]);
    float nn = tanhf(in + r * bb[512 + c]);
    float hv = (1.f - z) * nn;

    __nv_bfloat16 hi = __float2bfloat16(hv);
    __nv_bfloat16 lo = __float2bfloat16(hv - __bfloat162float(hi));
    __nv_bfloat16* h2 = g_h2 + (size_t)(dir * NKEY_ + n) * 512;
    h2[c] = hi; h2[256 + c] = lo;
}

__global__ void ksum2_kernel()
{
    int i = blockIdx.x * blockDim.x + threadIdx.x;
    if (i >= NKEY_ * H_) return;
    int n = i >> 8, c = i & 255;
    const __nv_bfloat16* hf = g_h2 + (size_t)n * 512;
    const __nv_bfloat16* hb = g_h2 + (size_t)(NKEY_ + n) * 512;
    float s = __bfloat162float(hf[c]) + __bfloat162float(hf[256 + c])
            + __bfloat162float(hb[c]) + __bfloat162float(hb[256 + c]);
    __nv_bfloat16 hi = __float2bfloat16(s);
    __nv_bfloat16 lo = __float2bfloat16(s - __bfloat162float(hi));
    __nv_bfloat16* y = g_ksum2 + (size_t)n * 512;
    y[c] = hi; y[256 + c] = lo;
}

// ---------------- unified prep: zeros + splits + bias concat ----------------
__global__ void prep_kernel(const float* __restrict__ emb,
                            const float* kWif, const float* kWib,
                            const float* eWif, const float* eWib,
                            const float* kWhf, const float* kWhb,
                            const float* kbif, const float* kbib,
                            const float* ebif, const float* ebib)
{
    const int N_EH  = 4 * B_ * H_;
    const int N_EMB = V_ * 320;
    const int SZP = 768 * 320, SZH = 768 * 256;
    const int N_W = 4 * SZP + 4 * SZH;
    const int total = N_EH + N_EMB + N_W + 3072;

    for (int i = blockIdx.x * blockDim.x + threadIdx.x; i < total;
         i += gridDim.x * blockDim.x) {
        int j = i;
        if (j < N_EH) { g_eh[j] = 0.f; continue; }
        j -= N_EH;
        if (j < N_EMB) {
            int r = j / 320, c = j - r * 320;
            float x = (c < 300) ? emb[(size_t)r * 300 + c] : 0.f;
            __nv_bfloat16 hi = __float2bfloat16(x);
            __nv_bfloat16 lo = __float2bfloat16(x - __bfloat162float(hi));
            __nv_bfloat16* y = g_emb2 + (size_t)r * 640;
            y[c] = hi; y[320 + c] = lo;
            continue;
        }
        j -= N_EMB;
        if (j < N_W) {
            if (j < 4 * SZP) {
                int seg = j / SZP, loc = j - seg * SZP;
                const int Kpad = 320, Cc = 300;
                const float* srcs[4] = {kWif, kWib, eWif, eWib};
                int lds[4] = {300, 300, 556, 556};
                const float* X = srcs[seg]; int ldx = lds[seg];
                __nv_bfloat16* Y = g_Wpre2 + (size_t)seg * 768 * 960;
                int r = loc / Kpad, c = loc - r * Kpad;
                float x = (c < Cc) ? X[(size_t)r * ldx + c] : 0.f;
                __nv_bfloat16 hi = __float2bfloat16(x);
                __nv_bfloat16 lo = __float2bfloat16(x - __bfloat162float(hi));
                __nv_bfloat16* y = Y + (size_t)r * 3 * Kpad;
                y[c] = hi; y[Kpad + c] = hi; y[2 * Kpad + c] = lo;
            } else {
                int jj = j - 4 * SZP;
                int seg = jj / SZH, loc = jj - seg * SZH;
                const int Kpad = 256;
                int r = loc / Kpad, c = loc - r * Kpad;
                const float* X; int ldx; __nv_bfloat16* Y;
                if (seg < 2) { X = seg ? kWhb : kWhf; ldx = 256;
                               Y = g_Whk2 + (size_t)seg * 768 * 768; }
                else         { X = (seg == 2) ? (eWif + 300) : (eWib + 300); ldx = 556;
                               Y = g_eW2 + (size_t)(seg - 2) * 768 * 768; }
                float x = X[(size_t)r * ldx + c];
                __nv_bfloat16 hi = __float2bfloat16(x);
                __nv_bfloat16 lo = __float2bfloat16(x - __bfloat162float(hi));
                __nv_bfloat16* y = Y + (size_t)r * 3 * Kpad;
                y[c] = hi; y[Kpad + c] = hi; y[2 * Kpad + c] = lo;
            }
            continue;
        }
        j -= N_W;
        float v;
        if      (j < 768)  v = kbif[j];
        else if (j < 1536) v = kbib[j - 768];
        else if (j < 2304) v = ebif[j - 1536];
        else               v = ebib[j - 2304];
        g_bcat[j] = v;
    }
}

// ---------------- persistent encoder BiGRU (per-stream barriers) ----------
__device__ __forceinline__ void gridbar_st(int st)
{
    __syncthreads();
    if (threadIdx.x == 0) {
        __threadfence();
        unsigned prev = atomicAdd(&g_barCnt4[st], 1u);
        unsigned target = (prev / 32u + 1u) * 32u;
        while (*(volatile unsigned*)&g_barCnt4[st] < target) { }
    }
    __syncthreads();
}

__global__ __launch_bounds__(256, 1) void enc_persistent_kernel(
    const float* __restrict__ Whf, const float* __restrict__ Whb,
    const float* __restrict__ bhf, const float* __restrict__ bhb)
{
    __shared__ float Hs[32][260];
    __shared__ float Wsh[24][260];
    __shared__ float bsh[24];

    const int t    = threadIdx.x;
    const int b    = blockIdx.x;
    const int st   = b & 3;
    const int c0   = (b >> 2) * 8;
    const float* Wh = (st & 1) ? Whb : Whf;
    const float* bh = (st & 1) ? bhb : bhf;
    const float* gix = g_gix + (size_t)(st >> 1) * BS_ * 1536;
    const int gbase = (st & 1) * 768;
    float* ehp = g_eh + st * B_ * H_;

    for (int li = t; li < 24 * 64; li += 256) {
        int r = li >> 6, kq = (li & 63) * 4;
        int wrow = (r >> 3) * 256 + c0 + (r & 7);
        *(float4*)&Wsh[r][kq] = *(const float4*)(Wh + (size_t)wrow * H_ + kq);
    }
    if (t < 24) bsh[t] = bh[(t >> 3) * 256 + c0 + (t & 7)];
    __syncthreads();

    const int lane = t & 31;
    const int warp = t >> 5;
    const int ch = c0 + warp;

    for (int step = 0; step < S_; step++) {
        for (int li = t; li < 32 * 64; li += 256) {
            int r = li >> 6, kq = (li & 63) * 4;
            float4 v = __ldcg((const float4*)(ehp + r * H_ + kq));
            *(float4*)&Hs[r][kq] = v;
        }
        __syncthreads();

        float accR = 0.f, accZ = 0.f, accN = 0.f;
#pragma unroll 8
        for (int k = 0; k < 64; k++) {
            float4 hv = *(const float4*)&Hs[lane][k * 4];
            float4 wr = *(const float4*)&Wsh[warp][k * 4];
            float4 wz = *(const float4*)&Wsh[8 + warp][k * 4];
            float4 wn = *(const float4*)&Wsh[16 + warp][k * 4];
            accR += hv.x*wr.x + hv.y*wr.y + hv.z*wr.z + hv.w*wr.w;
            accZ += hv.x*wz.x + hv.y*wz.y + hv.z*wz.z + hv.w*wz.w;
            accN += hv.x*wn.x + hv.y*wn.y + hv.z*wn.z + hv.w*wn.w;
        }

        int s   = (st & 1) ? (S_ - 1 - step) : step;
        int row = lane * S_ + s;
        const float* gi = gix + (size_t)row * 1536 + gbase;
        float ir = gi[ch], iz = gi[256 + ch], in = gi[512 + ch];
        float r  = sigf(ir + accR + bsh[warp]);
        float z  = sigf(iz + accZ + bsh[8 + warp]);
        float nn = tanhf(in + r * (accN + bsh[16 + warp]));
        float hv = (1.f - z) * nn + z * Hs[lane][ch];
        ehp[lane * H_ + ch] = hv;
        if (st == 0)      g_sc[(size_t)row * 512 + ch]       = hv;
        else if (st == 1) g_sc[(size_t)row * 512 + 256 + ch] = hv;

        gridbar_st(st);
    }
}

__global__ void rcopy_kernel()
{
    int i = blockIdx.x * blockDim.x + threadIdx.x;
    int b = i >> 9, c = i & 511;
    g_r[i] = (c < 256) ? g_eh[2 * B_ * H_ + b * 256 + c]
                       : g_eh[3 * B_ * H_ + b * 256 + (c - 256)];
}

// ---------------- SIMT GEMM for attention ----------------
__global__ __launch_bounds__(256) void gemm_sm(
    int M, int N, int K,
    const float* __restrict__ A, int lda,
    const float* __restrict__ W, int ldw,
    const float* __restrict__ bias,
    float* __restrict__ C, int ldc)
{
    __shared__ float Asx[16][128];
    __shared__ float Wsx[16][64];

    const int m0 = blockIdx.y * 128;
    const int n0 = blockIdx.x * 64;
    const int t  = threadIdx.x;
    const int tx = t & 15;
    const int ty = t >> 4;

    float acc[8][4];
#pragma unroll
    for (int i = 0; i < 8; i++)
#pragma unroll
        for (int j = 0; j < 4; j++) acc[i][j] = 0.f;

    for (int k0 = 0; k0 < K; k0 += 16) {
#pragma unroll
        for (int i = 0; i < 2; i++) {
            int li  = t + i * 256;
            int row = li >> 2;
            int kq  = (li & 3) * 4;
            float4 v = *(const float4*)(A + (size_t)(m0 + row) * lda + k0 + kq);
            Asx[kq + 0][row] = v.x; Asx[kq + 1][row] = v.y;
            Asx[kq + 2][row] = v.z; Asx[kq + 3][row] = v.w;
        }
        {
            int row = t >> 2;
            int kq  = (t & 3) * 4;
            float4 v = *(const float4*)(W + (size_t)(n0 + row) * ldw + k0 + kq);
            Wsx[kq + 0][row] = v.x; Wsx[kq + 1][row] = v.y;
            Wsx[kq + 2][row] = v.z; Wsx[kq + 3][row] = v.w;
        }
        __syncthreads();
#pragma unroll
        for (int kk = 0; kk < 16; kk++) {
            float4 a0 = *(const float4*)&Asx[kk][ty * 8];
            float4 a1 = *(const float4*)&Asx[kk][ty * 8 + 4];
            float4 w  = *(const float4*)&Wsx[kk][tx * 4];
            float av[8] = {a0.x, a0.y, a0.z, a0.w, a1.x, a1.y, a1.z, a1.w};
            float wv[4] = {w.x, w.y, w.z, w.w};
#pragma unroll
            for (int i = 0; i < 8; i++)
#pragma unroll
                for (int j = 0; j < 4; j++) acc[i][j] += av[i] * wv[j];
        }
        __syncthreads();
    }

#pragma unroll
    for (int i = 0; i < 8; i++) {
        int row = m0 + ty * 8 + i;
        float4 o;
        o.x = acc[i][0] + bias[n0 + tx * 4 + 0];
        o.y = acc[i][1] + bias[n0 + tx * 4 + 1];
        o.z = acc[i][2] + bias[n0 + tx * 4 + 2];
        o.w = acc[i][3] + bias[n0 + tx * 4 + 3];
        *(float4*)(C + (size_t)row * ldc + n0 + tx * 4) = o;
    }
}

// ---------------- attention tail ----------------
__device__ __forceinline__ float blockReduceSum(float v)
{
    __shared__ float sh[32];
    for (int o = 16; o; o >>= 1) v += __shfl_down_sync(0xffffffffu, v, o);
    int lane = threadIdx.x & 31, w = threadIdx.x >> 5;
    if (lane == 0) sh[w] = v;
    __syncthreads();
    int nw = (blockDim.x + 31) >> 5;
    v = (w == 0 && lane < nw) ? sh[lane] : 0.f;
    if (w == 0)
        for (int o = 16; o; o >>= 1) v += __shfl_down_sync(0xffffffffu, v, o);
    return v;
}

__global__ void energy_kernel()
{
    int bs = blockIdx.x;
    int b  = bs / S_;
    float p = 0.f;
    for (int k = threadIdx.x; k < 512; k += 128)
        p += g_a[(size_t)bs * 512 + k] * g_r[b * 512 + k];
    float s = blockReduceSum(p);
    if (threadIdx.x == 0) g_energy[bs] = s;
}

__global__ void softmax_kernel(const float* __restrict__ mask)
{
    int b = blockIdx.x;
    __shared__ float ex[S_];
    __shared__ float smx, ssum;
    int tid = threadIdx.x;
    if (tid < S_) ex[tid] = g_energy[b * S_ + tid];
    __syncthreads();
    if (tid == 0) { float m = -1e30f; for (int s = 0; s < S_; s++) m = fmaxf(m, ex[s]); smx = m; }
    __syncthreads();
    if (tid < S_) ex[tid] = __expf(ex[tid] - smx);
    __syncthreads();
    if (tid == 0) { float s = 0.f; for (int i = 0; i < S_; i++) s += ex[i]; ssum = s; }
    __syncthreads();
    if (tid < S_) g_alpha[b * S_ + tid] = ex[tid] / ssum * mask[b * S_ + tid];
}

__global__ void cattn_kernel()
{
    int b = blockIdx.x, d = threadIdx.x;
    float acc = 0.f;
    for (int s = 0; s < S_; s++)
        acc += g_alpha[b * S_ + s] * g_sc[(size_t)(b * S_ + s) * 512 + d];
    g_cattn[b * 512 + d] = acc;
}

__global__ void final_kernel(const float* __restrict__ Mm,
                             const float* __restrict__ b0,
                             float* __restrict__ out)
{
    int b = blockIdx.x;
    float part = 0.f;
    for (int d = threadIdx.x; d < 512; d += 256) {
        const float* mr = Mm + (size_t)d * 512;
        const float* rr = g_r + b * 512;
        float td = 0.f;
        for (int e = 0; e < 512; e++) td += mr[e] * rr[e];
        part += g_cattn[b * 512 + d] * td;
    }
    float s = blockReduceSum(part);
    if (threadIdx.x == 0) out[b] = s + b0[0];
}

// ---------------- host orchestration ----------------
extern "C" void kernel_launch(void* const* d_in, const int* in_sizes, int n_in,
                              void* d_out, int out_size)
{
    const int*   x1     = (const int*)d_in[0];
    const int*   x2     = (const int*)d_in[1];
    const int*   keys_c = (const int*)d_in[2];
    const int*   keys_r = (const int*)d_in[3];
    const float* x1mask = (const float*)d_in[4];
    const float* emb    = (const float*)d_in[5];
    const float* kWif   = (const float*)d_in[6];
    const float* kWhf   = (const float*)d_in[7];
    const float* kbif   = (const float*)d_in[8];
    const float* kbhf   = (const float*)d_in[9];
    const float* kWib   = (const float*)d_in[10];
    const float* kWhb   = (const float*)d_in[11];
    const float* kbib   = (const float*)d_in[12];
    const float* kbhb   = (const float*)d_in[13];
    const float* eWif   = (const float*)d_in[14];
    const float* eWhf   = (const float*)d_in[15];
    const float* ebif   = (const float*)d_in[16];
    const float* ebhf   = (const float*)d_in[17];
    const float* eWib   = (const float*)d_in[18];
    const float* eWhb   = (const float*)d_in[19];
    const float* ebib   = (const float*)d_in[20];
    const float* ebhb   = (const float*)d_in[21];
    const float* attn_W = (const float*)d_in[22];
    const float* attn_b = (const float*)d_in[23];
    const float* Mm     = (const float*)d_in[24];
    const float* b0     = (const float*)d_in[25];
    float* out = (float*)d_out;

    float *pP, *pBcat, *pGix, *pSc, *pA, *pGH;
    __nv_bfloat16 *pEmb2, *pWpre2, *pWhk2, *pEW2, *pH2, *pKsum2;
    cudaGetSymbolAddress((void**)&pP,     g_P);
    cudaGetSymbolAddress((void**)&pBcat,  g_bcat);
    cudaGetSymbolAddress((void**)&pGix,   g_gix);
    cudaGetSymbolAddress((void**)&pSc,    g_sc);
    cudaGetSymbolAddress((void**)&pA,     g_a);
    cudaGetSymbolAddress((void**)&pGH,    g_gh);
    cudaGetSymbolAddress((void**)&pEmb2,  g_emb2);
    cudaGetSymbolAddress((void**)&pWpre2, g_Wpre2);
    cudaGetSymbolAddress((void**)&pWhk2,  g_Whk2);
    cudaGetSymbolAddress((void**)&pEW2,   g_eW2);
    cudaGetSymbolAddress((void**)&pH2,    g_h2);
    cudaGetSymbolAddress((void**)&pKsum2, g_ksum2);

    cudaFuncSetAttribute(gemm_w64, cudaFuncAttributeMaxDynamicSharedMemorySize,
                         GW64_SMEM);

    // second stream + fork/join events (created once, outside graph capture;
    // reused identically on every call -> deterministic captured graph)
    static cudaStream_t s2 = nullptr;
    static cudaEvent_t evF = nullptr, evJ = nullptr;
    if (!s2) {
        cudaStreamCreateWithFlags(&s2, cudaStreamNonBlocking);
        cudaEventCreateWithFlags(&evF, cudaEventDisableTiming);
        cudaEventCreateWithFlags(&evJ, cudaEventDisableTiming);
    }

    // 0: unified prep (zeros + bf16 splits + bias concat)
    prep_kernel<<<8192, 256>>>(emb, kWif, kWib, eWif, eWib, kWhf, kWhb,
                               kbif, kbib, ebif, ebib);

    // 1: unified precompute GEMM  g_P = emb2 @ [kWif;kWib;eWif;eWib]^T + bcat
    mgemm(V_, 3072, 960, 640, pEmb2, 640, pWpre2, 960, pBcat, pP, 3072);

    // 2: key BiGRU t=0 (h=0 -> gh=bias), both dirs
    key_gates0_kernel<<<dim3(NKEY_, 2), 256>>>(keys_c, keys_r, kbhf, kbhb);

    // fork: backward chain runs on s2 concurrently with forward on default
    cudaEventRecord(evF, 0);
    cudaStreamWaitEvent(s2, evF, 0);

    for (int t = 1; t < KK_; t++) {
        // forward dir on default stream
        mgemm(NKEY_, G3_, 768, 512, pH2, 512, pWhk2, 768, kbhf, pGH, G3_,
              nullptr, nullptr, 0, 0, nullptr, nullptr, 0,
              nullptr, 0x7fffffff, 0);
        key_gates_kernel<<<NKEY_ / 4, 256>>>(keys_c, keys_r, t, 0);
        // backward dir on s2
        mgemm(NKEY_, G3_, 768, 512, pH2 + (size_t)NKEY_ * 512, 512,
              pWhk2 + 768 * 768, 768, kbhb, pGH + (size_t)NKEY_ * G3_, G3_,
              nullptr, nullptr, 0, 0, nullptr, nullptr, 0,
              nullptr, 0x7fffffff, s2);
        key_gates_kernel<<<NKEY_ / 4, 256, 0, s2>>>(keys_c, keys_r, t, 1);
    }

    // join
    cudaEventRecord(evJ, s2);
    cudaStreamWaitEvent(0, evJ, 0);

    ksum2_kernel<<<(NKEY_ * H_ + 255) / 256, 256>>>();

    // encoder input projections: ONE merged GEMM (x1 rows then x2 rows)
    mgemm(NKEY_, 1536, 768, 512, pKsum2, 512, pEW2, 768, nullptr,
          pGix, 1536, x1, pP, 3072, 1536,
          nullptr, nullptr, 0, x2, BS_);

    // encoder BiGRU: persistent, per-stream barriers
    enc_persistent_kernel<<<128, 256>>>(eWhf, eWhb, ebhf, ebhb);
    rcopy_kernel<<<64, 256>>>();

    // attention + output
    {
        dim3 g(512 / 64, BS_ / 128);
        gemm_sm<<<g, 256>>>(BS_, 512, 512, pSc, 512, attn_W, 512, attn_b, pA, 512);
    }
    energy_kernel<<<BS_, 128>>>();
    softmax_kernel<<<B_, 192>>>(x1mask);
    cattn_kernel<<<B_, 512>>>();
    final_kernel<<<B_, 256>>>(Mm, b0, out);
}